// round 15
// baseline (speedup 1.0000x reference)
#include <cuda_runtime.h>
#include <cuda_fp16.h>
#include <math.h>
#include <stdint.h>

// Problem constants
#define B_   8
#define C_   256
#define N_   4096
#define TK   64       // keys per tile
#define OCH  320      // 32 (wq=f) + 32 (wk=g) + 256 (wv=h)
#define L2E  1.44269504f

// ---------------- scratch (device globals; no cudaMalloc allowed) ----------
__device__ __align__(16) __half g_Wh[OCH * C_];      // concat weights fp16
__device__ __align__(16) float  g_bias[OCH];
__device__ __align__(16) __half g_xT[(size_t)B_ * N_ * C_];   // x fp16 [b][n][c]
// q/k: [b][n][64] fp16 rows (only cols 0-31 meaningful; 128B row stride)
// NOTE: g_Qt rows are pre-scaled by log2(e) so QK MMA emits log2-domain scores.
__device__ __align__(16) __half g_Qt[(size_t)B_ * N_ * 64];
__device__ __align__(16) __half g_Kt[(size_t)B_ * N_ * 64];
// v channels: [b][c][n] fp16
__device__ __align__(16) __half g_Hv[(size_t)B_ * C_ * N_];

// ---------------- fp16 helpers ------------------------------------------------
__device__ __forceinline__ uint32_t pkh2(float lo, float hi) {
    uint32_t r;
    asm("cvt.rn.f16x2.f32 %0, %1, %2;" : "=r"(r) : "f"(hi), "f"(lo));
    return r;
}
__device__ __forceinline__ uint32_t h2ex2(uint32_t t) {
    uint32_t r;
    asm("ex2.approx.f16x2 %0, %1;" : "=r"(r) : "r"(t));
    return r;
}

// ---------------- warp MMA / ldmatrix / cp.async (portable sm_80+) -----------
__device__ __forceinline__ uint32_t smem_u32(const void* p) {
    return (uint32_t)__cvta_generic_to_shared(p);
}
__device__ __forceinline__ void ldsm4(uint32_t& a, uint32_t& b, uint32_t& c,
                                      uint32_t& d, uint32_t addr) {
    asm volatile("ldmatrix.sync.aligned.m8n8.x4.shared.b16 {%0,%1,%2,%3}, [%4];"
                 : "=r"(a), "=r"(b), "=r"(c), "=r"(d) : "r"(addr));
}
__device__ __forceinline__ void mma_f16(float* c, const uint32_t* a,
                                        uint32_t b0, uint32_t b1) {
    asm volatile(
        "mma.sync.aligned.m16n8k16.row.col.f32.f16.f16.f32 "
        "{%0,%1,%2,%3}, {%4,%5,%6,%7}, {%8,%9}, {%0,%1,%2,%3};"
        : "+f"(c[0]), "+f"(c[1]), "+f"(c[2]), "+f"(c[3])
        : "r"(a[0]), "r"(a[1]), "r"(a[2]), "r"(a[3]), "r"(b0), "r"(b1));
}
__device__ __forceinline__ void cpa16(uint32_t dst, const void* src) {
    asm volatile("cp.async.cg.shared.global [%0], [%1], 16;"
                 :: "r"(dst), "l"(src) : "memory");
}
#define CP_COMMIT() asm volatile("cp.async.commit_group;" ::: "memory")
#define CP_WAIT1()  asm volatile("cp.async.wait_group 1;" ::: "memory")

// SW128 swizzle on byte offsets within 128B rows
#define SWZ(o) ((o) ^ (((o) >> 3) & 0x70))

// ---------------- kernel 0: concat weights (fp16) + biases -------------------
__global__ void concat_kernel(const float* __restrict__ wq, const float* __restrict__ bq,
                              const float* __restrict__ wk, const float* __restrict__ bk,
                              const float* __restrict__ wv, const float* __restrict__ bv) {
    int idx = blockIdx.x * 256 + threadIdx.x;
    if (idx < 32 * C_)            g_Wh[idx] = __float2half(wq[idx]);
    else if (idx < 64 * C_)       g_Wh[idx] = __float2half(wk[idx - 32 * C_]);
    else if (idx < OCH * C_)      g_Wh[idx] = __float2half(wv[idx - 64 * C_]);
    int j = idx - OCH * C_;
    if (j >= 0 && j < OCH)
        g_bias[j] = (j < 32) ? bq[j] : (j < 64) ? bk[j - 32] : bv[j - 64];
}

// ---------------- kernel 0b: transpose+convert x -> xT fp16 [b][n][c] --------
__global__ void __launch_bounds__(256)
xcvt_kernel(const float* __restrict__ x) {
    __shared__ float t[64][65];
    const int tid = threadIdx.x;
    const int n0  = blockIdx.x * 64;
    const int c0  = blockIdx.y * 64;
    const int bb  = blockIdx.z;

    #pragma unroll
    for (int r = 0; r < 16; r++) {
        int idx = tid + r * 256;
        int c = idx >> 6, n = idx & 63;
        t[c][n] = x[((size_t)bb * C_ + c0 + c) * N_ + n0 + n];
    }
    __syncthreads();
    #pragma unroll
    for (int r = 0; r < 8; r++) {
        int idx = tid + r * 256;
        int n = idx >> 5, cp = idx & 31;
        size_t off = ((size_t)bb * N_ + n0 + n) * C_ + c0 + cp * 2;
        *(uint32_t*)(g_xT + off) = pkh2(t[cp * 2][n], t[cp * 2 + 1][n]);
    }
}

// ---------------- kernel 1: projection GEMM on mma.sync ----------------------
#define PJ_A    0        // 4 chunks x 8KB = 32KB (also reused as fp16 stage)
#define PJ_B    32768    // 2 x 16KB
#define PJ_SMEM 65536

__global__ void __launch_bounds__(256)
proj_mma() {
    extern __shared__ char psm[];
    const uint32_t sbase = smem_u32(psm);
    const int tid  = threadIdx.x;
    const int lane = tid & 31;
    const int wid  = tid >> 5;
    const int wm   = wid & 3;        // o 16-row group
    const int wn   = wid >> 2;       // n 64-col group
    const int n0   = blockIdx.x * 128;
    const int bb   = blockIdx.y;
    const int o0   = blockIdx.z * 64;

    const __half* xT = g_xT + (size_t)bb * N_ * C_;

    #pragma unroll
    for (int r = 0; r < 8; r++) {
        int idx = tid + r * 256;
        int o = idx >> 5, k8 = idx & 31;
        int chunk = k8 >> 3, kin = k8 & 7;
        *(uint4*)(psm + PJ_A + chunk * 8192 + SWZ(o * 128 + kin * 16)) =
            *(const uint4*)(g_Wh + (size_t)(o0 + o) * C_ + k8 * 8);
    }
    #pragma unroll
    for (int r = 0; r < 4; r++) {
        int idx = tid + r * 256;
        int n = idx >> 3, kin = idx & 7;
        cpa16(sbase + PJ_B + SWZ(n * 128 + kin * 16),
              xT + (size_t)(n0 + n) * C_ + kin * 8);
    }
    CP_COMMIT();

    const int frow = lane & 15;
    const int fsel = (lane >> 4) * 16;

    float acc[8][4];
    #pragma unroll
    for (int i = 0; i < 8; i++)
        #pragma unroll
        for (int v = 0; v < 4; v++) acc[i][v] = 0.0f;

    for (int kc = 0; kc < 4; kc++) {
        __syncthreads();
        {
            int nk = (kc + 1) & 3;
            int nb = (kc + 1) & 1;
            #pragma unroll
            for (int r = 0; r < 4; r++) {
                int idx = tid + r * 256;
                int n = idx >> 3, kin = idx & 7;
                cpa16(sbase + PJ_B + nb * 16384 + SWZ(n * 128 + kin * 16),
                      xT + (size_t)(n0 + n) * C_ + nk * 64 + kin * 8);
            }
            CP_COMMIT();
        }
        CP_WAIT1();
        __syncthreads();

        const int cb = kc & 1;
        uint32_t Af[4][4];
        #pragma unroll
        for (int ks = 0; ks < 4; ks++)
            ldsm4(Af[ks][0], Af[ks][1], Af[ks][2], Af[ks][3],
                  sbase + PJ_A + kc * 8192 +
                  SWZ((16 * wm + frow) * 128 + ks * 32 + fsel));
        #pragma unroll
        for (int ks = 0; ks < 4; ks++) {
            #pragma unroll
            for (int g = 0; g < 4; g++) {
                uint32_t Bf[4];
                ldsm4(Bf[0], Bf[1], Bf[2], Bf[3],
                      sbase + PJ_B + cb * 16384 +
                      SWZ((64 * wn + 16 * g + frow) * 128 + ks * 32 + fsel));
                mma_f16(acc[2 * g + 0], Af[ks], Bf[0], Bf[2]);
                mma_f16(acc[2 * g + 1], Af[ks], Bf[1], Bf[3]);
            }
        }
    }
    __syncthreads();

    const int r_lo = 16 * wm + (lane >> 2);
    const int r_hi = r_lo + 8;
    const float b_lo = g_bias[o0 + r_lo];
    const float b_hi = g_bias[o0 + r_hi];
    __half* st = (__half*)psm;

    if (o0 == 0) {
        // g rows (32-63) pre-scaled by log2(e) for the log2-domain softmax
        const float sc_lo = (r_lo >= 32) ? L2E : 1.0f;
        const float sc_hi = (r_hi >= 32) ? L2E : 1.0f;
        #pragma unroll
        for (int nt = 0; nt < 8; nt++) {
            int n = 64 * wn + 8 * nt + 2 * (lane & 3);
            st[n * 64 + r_lo]       = __float2half((acc[nt][0] + b_lo) * sc_lo);
            st[(n + 1) * 64 + r_lo] = __float2half((acc[nt][1] + b_lo) * sc_lo);
            st[n * 64 + r_hi]       = __float2half((acc[nt][2] + b_hi) * sc_hi);
            st[(n + 1) * 64 + r_hi] = __float2half((acc[nt][3] + b_hi) * sc_hi);
        }
        __syncthreads();
        #pragma unroll
        for (int r = 0; r < 8; r++) {
            int idx = tid + r * 256;
            int n = idx >> 4, c8 = idx & 15;
            if (c8 < 8) {
                *(uint2*)(g_Kt + ((size_t)bb * N_ + n0 + n) * 64 + c8 * 4) =
                    *(const uint2*)(st + n * 64 + c8 * 4);
            } else {
                *(uint2*)(g_Qt + ((size_t)bb * N_ + n0 + n) * 64 + (c8 - 8) * 4) =
                    *(const uint2*)(st + n * 64 + 32 + (c8 - 8) * 4);
            }
        }
    } else {
        #pragma unroll
        for (int nt = 0; nt < 8; nt++) {
            int n = 64 * wn + 8 * nt + 2 * (lane & 3);
            st[r_lo * 128 + n]     = __float2half(acc[nt][0] + b_lo);
            st[r_lo * 128 + n + 1] = __float2half(acc[nt][1] + b_lo);
            st[r_hi * 128 + n]     = __float2half(acc[nt][2] + b_hi);
            st[r_hi * 128 + n + 1] = __float2half(acc[nt][3] + b_hi);
        }
        __syncthreads();
        #pragma unroll
        for (int r = 0; r < 4; r++) {
            int idx = tid + r * 256;
            int o = idx >> 4, n16 = idx & 15;
            *(uint4*)(g_Hv + ((size_t)bb * C_ + (o0 - 64) + o) * N_ + n0 + n16 * 8) =
                *(const uint4*)(st + o * 128 + n16 * 8);
        }
    }
}

// ---------------- kernel 2: flash attention, q16-owner warps -----------------
// CTA: 128 q-rows x 128 channels (c-half). grid (N/128, 2, B).
// 3-stage cp.async ring, ONE __syncthreads per tile:
//   wait_group(1) -> barrier -> prefetch it+2 over it-1's buffer -> compute it.
// Softmax in log2 domain, P via ex2.f16x2 straight into A-frags, l via ones-MMA.
// SMEM (bytes):
#define OFF_Q    0        // 128 x 128B = 16KB (first 64B/row used)
#define OFF_S    16384    // 3 stages x (K 8KB + V 16KB)
#define STG      24576
#define OFF_SH   90112    // 128 floats (per-q shift, log2 domain)
#define FLASH_SMEM 90624  // epilogue reuses [0, 67584) as ts[128][132] f32

__global__ void __launch_bounds__(256, 2)
flash_mma(const float* __restrict__ x, const float* __restrict__ gamma,
          float* __restrict__ out) {
    extern __shared__ char sm[];
    const uint32_t sbase = smem_u32(sm);
    const int tid  = threadIdx.x;
    const int lane = tid & 31;
    const int wid  = tid >> 5;
    const int bb   = blockIdx.z;
    const int c0   = blockIdx.y * 128;
    const int j0   = blockIdx.x * 128;

    const __half* Qt = g_Qt + (size_t)bb * N_ * 64;
    const __half* Kt = g_Kt + (size_t)bb * N_ * 64;
    const __half* Hv = g_Hv + ((size_t)bb * C_ + c0) * N_;
    float* sh_s = (float*)(sm + OFF_SH);

    // per-thread load geometry (precomputed swizzle XORs)
    const int krow = tid >> 2, kk = tid & 3;                 // K: 64 rows x 4
    const uint32_t kdst = (uint32_t)(krow * 128 + kk * 16) ^ ((krow & 7) << 4);
    const __half* kp = Kt + krow * 64 + kk * 8;
    const uint32_t vdst0 = (uint32_t)(((tid >> 3) & 31) * 128 + (tid & 7) * 16)
                           ^ (((tid >> 3) & 7) << 4);        // V row tid>>3, +32/t
    const __half* vp = Hv + (size_t)(tid >> 3) * N_ + (tid & 7) * 8;

    // ---- prologue: Q tile + shifts + async tiles 0,1 ----
    #pragma unroll
    for (int t = 0; t < 2; t++) {
        int idx = tid + t * 256, row = idx >> 2, k = idx & 3;
        uint4 v = *(const uint4*)(Qt + (size_t)(j0 + row) * 64 + k * 8);
        *(uint4*)(sm + OFF_Q + (uint32_t)((row * 128 + k * 16) ^ ((row & 7) << 4))) = v;
    }
    if (tid < 128) {
        const __half* row = Qt + (size_t)(j0 + tid) * 64;
        float s = 0.0f;
        #pragma unroll 8
        for (int d = 0; d < 32; d++) {
            float v = __half2float(row[d]);
            s += v * v;
        }
        sh_s[tid] = 3.26f * sqrtf(s);   // rows pre-scaled by L2E -> log2 domain
    }
    #pragma unroll
    for (int pt = 0; pt < 2; pt++) {    // tiles 0,1 -> stages 0,1
        uint32_t sb = sbase + OFF_S + pt * STG;
        cpa16(sb + kdst, kp + pt * 4096);
        #pragma unroll
        for (int t = 0; t < 4; t++)
            cpa16(sb + 8192 + vdst0 + t * 4096, vp + (size_t)t * 32 * N_ + pt * 64);
        CP_COMMIT();
    }
    __syncthreads();

    // hoisted Q A-frags (q16 x d32)
    const int frow = lane & 15;
    const int fsel = (lane >> 4) * 16;
    const int r0 = 16 * wid + (lane >> 2);
    const uint32_t fxor  = (uint32_t)((frow & 7) << 4);
    const uint32_t fbase = (uint32_t)(frow * 128 + fsel);    // + g*2048 + ks*32
    uint32_t A[2][4];
    #pragma unroll
    for (int kc = 0; kc < 2; kc++)
        ldsm4(A[kc][0], A[kc][1], A[kc][2], A[kc][3],
              (sbase + OFF_Q + fbase + 16 * wid * 128 + kc * 32) ^ fxor);
    const float nsh0 = -sh_s[r0], nsh1 = -sh_s[r0 + 8];
    const uint32_t ONES = 0x3C003C00u;     // (1.0h, 1.0h)

    float o[16][4];
    #pragma unroll
    for (int i = 0; i < 16; i++)
        #pragma unroll
        for (int v = 0; v < 4; v++) o[i][v] = 0.0f;
    float lC[4] = {0.0f, 0.0f, 0.0f, 0.0f};   // l = P.ones C-frag (persistent)

    int cs = 0, ps = 2;                   // compute / prefetch stage indices
    for (int it = 0; it < N_ / TK; ++it) {
        CP_WAIT1();          // tile it complete (it+1 may be in flight)
        __syncthreads();     // publish tile it; all warps done with tile it-1

        {   // prefetch tile it+2 into stage ps (tile it-1's buffer)
            int nk = (it + 2) & 63;
            uint32_t sb = sbase + OFF_S + ps * STG;
            cpa16(sb + kdst, kp + nk * 4096);
            #pragma unroll
            for (int t = 0; t < 4; t++)
                cpa16(sb + 8192 + vdst0 + t * 4096, vp + (size_t)t * 32 * N_ + nk * 64);
            CP_COMMIT();
        }

        const uint32_t sKb = sbase + OFF_S + cs * STG + fbase;
        const uint32_t sVb = sKb + 8192;

        // ---- QK + softmax: t = q.k*log2e - sh via C-frag init; p = 2^t ----
        uint32_t Pk[4][4];
        #pragma unroll
        for (int kg = 0; kg < 4; kg++) {
            uint32_t Bf[2][4];
            #pragma unroll
            for (int kc = 0; kc < 2; kc++)
                ldsm4(Bf[kc][0], Bf[kc][1], Bf[kc][2], Bf[kc][3],
                      (sKb + kg * 2048 + kc * 32) ^ fxor);
            float s0[4] = {nsh0, nsh0, nsh1, nsh1};
            float s1[4] = {nsh0, nsh0, nsh1, nsh1};
            mma_f16(s0, A[0], Bf[0][0], Bf[0][2]);
            mma_f16(s0, A[1], Bf[1][0], Bf[1][2]);
            mma_f16(s1, A[0], Bf[0][1], Bf[0][3]);
            mma_f16(s1, A[1], Bf[1][1], Bf[1][3]);
            Pk[kg][0] = h2ex2(pkh2(s0[0], s0[1]));
            Pk[kg][1] = h2ex2(pkh2(s0[2], s0[3]));
            Pk[kg][2] = h2ex2(pkh2(s1[0], s1[1]));
            Pk[kg][3] = h2ex2(pkh2(s1[2], s1[3]));
            mma_f16(lC, Pk[kg], ONES, ONES);   // l += sum_k p
        }

        // ---- PV: o[q16][c128] += P[q16][k64] * V[c][k] -----------------------
        #pragma unroll
        for (int g = 0; g < 8; g++) {
            #pragma unroll
            for (int ks = 0; ks < 4; ks++) {
                uint32_t Vf[4];
                ldsm4(Vf[0], Vf[1], Vf[2], Vf[3],
                      (sVb + g * 2048 + ks * 32) ^ fxor);
                mma_f16(o[2 * g + 0], Pk[ks], Vf[0], Vf[2]);
                mma_f16(o[2 * g + 1], Pk[ks], Vf[1], Vf[3]);
            }
        }

        if (++cs == 3) cs = 0;
        if (++ps == 3) ps = 0;
    }

    // ---- epilogue: all cols of lC are Sum_k p; no reduction needed ----
    const float g0 = gamma[0];
    const float li0 = g0 / lC[0], li1 = g0 / lC[2];

    __syncthreads();
    float* ts = (float*)sm;    // [128c][132] fp32
    #pragma unroll
    for (int t = 0; t < 16; t++) {
        int cl = 8 * t + 2 * (lane & 3);
        ts[cl * 132 + r0]           = o[t][0] * li0;
        ts[(cl + 1) * 132 + r0]     = o[t][1] * li0;
        ts[cl * 132 + r0 + 8]       = o[t][2] * li1;
        ts[(cl + 1) * 132 + r0 + 8] = o[t][3] * li1;
    }
    __syncthreads();

    const float* xb = x   + ((size_t)bb * C_ + c0) * N_;
    float*       ob = out + ((size_t)bb * C_ + c0) * N_;
    #pragma unroll
    for (int r = 0; r < 16; r++) {
        int idx = tid + r * 256;           // 0..4095 float4s over 128c x 128q
        int c = idx >> 5, q4 = idx & 31;
        float4 xv = *(const float4*)&xb[(size_t)c * N_ + j0 + q4 * 4];
        float4 tv = *(const float4*)&ts[c * 132 + q4 * 4];
        float4 ov = make_float4(tv.x + xv.x, tv.y + xv.y, tv.z + xv.z, tv.w + xv.w);
        *(float4*)&ob[(size_t)c * N_ + j0 + q4 * 4] = ov;
    }
}

// ---------------- launch ------------------------------------------------------
extern "C" void kernel_launch(void* const* d_in, const int* in_sizes, int n_in,
                              void* d_out, int out_size) {
    (void)in_sizes; (void)n_in; (void)out_size;
    const float* x     = (const float*)d_in[0];
    const float* wq    = (const float*)d_in[1];
    const float* bq    = (const float*)d_in[2];
    const float* wk    = (const float*)d_in[3];
    const float* bk    = (const float*)d_in[4];
    const float* wv    = (const float*)d_in[5];
    const float* bv    = (const float*)d_in[6];
    const float* gamma = (const float*)d_in[7];
    float* out = (float*)d_out;

    cudaFuncSetAttribute(proj_mma, cudaFuncAttributeMaxDynamicSharedMemorySize,
                         PJ_SMEM);
    cudaFuncSetAttribute(flash_mma, cudaFuncAttributeMaxDynamicSharedMemorySize,
                         FLASH_SMEM);

    concat_kernel<<<322, 256>>>(wq, bq, wk, bk, wv, bv);
    xcvt_kernel<<<dim3(N_ / 64, C_ / 64, B_), 256>>>(x);
    proj_mma<<<dim3(N_ / 128, B_, OCH / 64), 256, PJ_SMEM>>>();
    flash_mma<<<dim3(N_ / 128, 2, B_), 256, FLASH_SMEM>>>(x, gamma, out);
}